// round 15
// baseline (speedup 1.0000x reference)
#include <cuda_runtime.h>

#define NT 64
typedef unsigned long long u64;

__device__ __forceinline__ u64 pk2(float x, float y) {
    u64 r; asm("mov.b64 %0,{%1,%2};" : "=l"(r) : "f"(x), "f"(y)); return r;
}
__device__ __forceinline__ void upk2(u64 v, float& x, float& y) {
    asm("mov.b64 {%0,%1},%2;" : "=f"(x), "=f"(y) : "l"(v));
}
__device__ __forceinline__ u64 ffma2(u64 a, u64 b, u64 c) {
    u64 d; asm("fma.rn.f32x2 %0,%1,%2,%3;" : "=l"(d) : "l"(a), "l"(b), "l"(c)); return d;
}

// packed butterfly over pair-index bit B
template <int B>
__device__ __forceinline__ void vstage(u64* v, float t) {
    u64 tp = pk2(t, t), tn = pk2(-t, -t);
#pragma unroll
    for (int a = 0; a < 32; ++a)
        if (!(a & (1 << B))) {
            u64 A = v[a], Bv = v[a | (1 << B)];
            v[a]            = ffma2(tn, Bv, A);
            v[a | (1 << B)] = ffma2(tp, A, Bv);
        }
}

// register-pair index for pass-1 load row-pair q: a = (f0^{-1}(2q)) >> 1
__device__ __forceinline__ constexpr int AQ(int q) {
    int q0 = q & 1, q1 = (q >> 1) & 1, q2 = (q >> 2) & 1, q3 = (q >> 3) & 1, q4 = (q >> 4) & 1;
    return (q0 ^ q1 ^ q2) | ((q1 ^ q2) << 1) | ((q2 ^ q3 ^ q4) << 2)
         | ((q3 ^ q4) << 3) | (q4 << 4);
}

#define PITCH 68

__global__ void __launch_bounds__(NT, 11)
qsim_kernel(const float* __restrict__ feats,
            const float* __restrict__ qp,
            float* __restrict__ out)
{
    // layout T: element (i_lo, i_hi) at i_lo*PITCH + i_hi  (pad 68 -> bank rot by 4/row)
    __shared__ float buf[64 * PITCH];
    __shared__ float tt[240];
    __shared__ float wred[2], gred[2];
    __shared__ float oscale_s;
    __shared__ float rsum[2][12];

    const int u    = threadIdx.x;   // 0..63
    const int lane = u & 31;
    const int b    = blockIdx.x;

    // tan table + global cos product (cos factors -> output scale G^2)
    float gpart = 1.0f;
    for (int i = u; i < 240; i += NT) {
        float s, c; sincosf(0.5f * qp[12 + i], &s, &c);
        tt[i] = s / c; gpart *= c;
    }
#pragma unroll
    for (int o = 16; o; o >>= 1) gpart *= __shfl_xor_sync(~0u, gpart, o);
    if (lane == 0) gred[u >> 5] = gpart;

    // embedding: raw state into T layout (elem s at (s&63)*PITCH + (s>>6))
    const float2* f2 = reinterpret_cast<const float2*>(feats + (size_t)b * 2048);
    const float PIO2 = 1.5707963267948966f;
    float acc = 8.0f;
#pragma unroll
    for (int v = 0; v < 16; ++v) {
        int p = v * 64 + u;
        float2 x = f2[p];
        float y0 = tanhf(x.x) * PIO2;
        float y1 = tanhf(x.y) * PIO2;
        acc += y0 * y0 + y1 * y1;
        int s = 2 * p;
        buf[(s & 63) * PITCH + (s >> 6)]       = y0;
        buf[((s + 1) & 63) * PITCH + (s >> 6)] = y1;
    }
#pragma unroll
    for (int v = 16; v < 32; ++v) {
        int s = 2 * (v * 64 + u);
        buf[(s & 63) * PITCH + (s >> 6)]       = 0.5f;
        buf[((s + 1) & 63) * PITCH + (s >> 6)] = 0.5f;
    }
#pragma unroll
    for (int o = 16; o; o >>= 1) acc += __shfl_xor_sync(~0u, acc, o);
    if (lane == 0) wred[u >> 5] = acc;
    __syncthreads();
    if (u == 0) {
        float G = gred[0] * gred[1];
        oscale_s = (G * G) / (wred[0] + wred[1]);
    }

    // per-thread constants
    // i_hi = H(u) = Mhi^{-1}(u)
    int u0 = u & 1, u1 = (u >> 1) & 1, u2b = (u >> 2) & 1;
    int u3 = (u >> 3) & 1, u4 = (u >> 4) & 1, u5 = (u >> 5) & 1;
    int Hh = (u0 ^ u1) | ((u1 ^ u2b ^ u3) << 1) | ((u2b ^ u3) << 2)
           | ((u3 ^ u4 ^ u5) << 3) | ((u4 ^ u5) << 4) | (u5 << 5);
    int e = u0 ^ u1;                         // i6 of this thread's dst block
    const float* pL = buf + u;               // pass-1 load base (col u, + m*PITCH imm)
    float* B0 = buf + Hh + (e ? 32 * PITCH : 0);   // pass-1 store, rows 0..31
    float* B1 = buf + Hh + (e ? 0 : 32 * PITCH);   // pass-1 store, rows 32..63
    float* pld = buf + u * PITCH;            // pass-2 base (in-place)
    float esgn = e ? -1.0f : 1.0f;

#pragma unroll 1
    for (int L = 0; L < 20; ++L) {
        const float* tc = &tt[L * 12];

        // ===== pass 1: entangling gather (addressing-free) + RY qubits 11..6 =====
        u64 vr[32];
        {
            float t11 = tc[11];
#pragma unroll
            for (int q = 0; q < 32; ++q) {
                float A  = pL[(2 * q) * PITCH];
                float Bv = pL[(2 * q + 1) * PITCH];
                // q11 fold computed scalar-form; role (which row holds comp0)
                // is compile-time: comp0 src = (q&1)? Bv : A.
                float c0, c1;
                if ((q & 1) == 0) {
                    c0 = fmaf(-t11, Bv, A);
                    c1 = fmaf( t11, A, Bv);
                } else {
                    c0 = fmaf(-t11, A, Bv);
                    c1 = fmaf( t11, Bv, A);
                }
                vr[AQ(q)] = pk2(c0, c1);
            }
        }
        vstage<0>(vr, tc[10]);
        vstage<1>(vr, tc[9]);
        vstage<2>(vr, tc[8]);
        vstage<3>(vr, tc[7]);
        vstage<4>(vr, esgn * tc[6]);   // e-swapped pairing on bit5 => R(-t)
        __syncthreads();               // all gathers done before rows are overwritten
#pragma unroll
        for (int a = 0; a < 16; ++a) {
            float x, y; upk2(vr[a], x, y);
            B0[(2 * a) * PITCH]     = x;
            B0[(2 * a + 1) * PITCH] = y;
        }
#pragma unroll
        for (int a = 16; a < 32; ++a) {
            float x, y; upk2(vr[a], x, y);
            B1[(2 * a - 32) * PITCH] = x;
            B1[(2 * a - 31) * PITCH] = y;
        }
        __syncthreads();

        // ===== pass 2: linear in-place, RY qubits 5..0 =====
        // fold q5 (component, scalar on fresh loads) and q4 (packed) into the load
        u64 vp[32];
        {
            float t5 = tc[5], t4 = tc[4];
            u64 tn4 = pk2(-t4, -t4), tp4 = pk2(t4, t4);
#pragma unroll
            for (int g = 0; g < 16; ++g) {
                float4 f = *reinterpret_cast<const float4*>(pld + 4 * g);
                float a0 = fmaf(-t5, f.y, f.x);
                float a1 = fmaf( t5, f.x, f.y);
                float b0 = fmaf(-t5, f.w, f.z);
                float b1 = fmaf( t5, f.z, f.w);
                u64 lo = pk2(a0, a1), hi = pk2(b0, b1);
                vp[2 * g]     = ffma2(tn4, hi, lo);   // q4 across i7
                vp[2 * g + 1] = ffma2(tp4, lo, hi);
            }
        }
        vstage<1>(vp, tc[3]);
        vstage<2>(vp, tc[2]);
        vstage<3>(vp, tc[1]);
        vstage<4>(vp, tc[0]);

        if (L < 19) {
#pragma unroll
            for (int g = 0; g < 16; ++g) {
                float x0, y0, x1, y1;
                upk2(vp[2 * g], x0, y0);
                upk2(vp[2 * g + 1], x1, y1);
                *reinterpret_cast<float4*>(pld + 4 * g) = make_float4(x0, y0, x1, y1);
            }
            __syncthreads();
        } else {
            // ===== expvals from registers =====
            // component = i6 (q5); pair bits b0..b4 = i7..i11 (q4..q0); u = i0..i5 (q11..q6)
            float S = 0.f, Ty = 0.f, T0 = 0.f, T1 = 0.f, T2 = 0.f, T3 = 0.f, T4 = 0.f;
#pragma unroll
            for (int a = 0; a < 32; ++a) {
                float x, y; upk2(vp[a], x, y);
                float px = x * x, py = y * y, ps = px + py;
                S += ps; Ty += py;
                if (a & 1)  T0 += ps;
                if (a & 2)  T1 += ps;
                if (a & 4)  T2 += ps;
                if (a & 8)  T3 += ps;
                if (a & 16) T4 += ps;
            }
            float val[12];
            val[0] = S - 2.f * T4;
            val[1] = S - 2.f * T3;
            val[2] = S - 2.f * T2;
            val[3] = S - 2.f * T1;
            val[4] = S - 2.f * T0;
            val[5] = S - 2.f * Ty;
#pragma unroll
            for (int q = 6; q < 12; ++q)
                val[q] = ((u >> (11 - q)) & 1) ? -S : S;
#pragma unroll
            for (int q = 0; q < 12; ++q) {
#pragma unroll
                for (int o = 16; o; o >>= 1)
                    val[q] += __shfl_xor_sync(~0u, val[q], o);
            }
            if (lane == 0) {
#pragma unroll
                for (int q = 0; q < 12; ++q) rsum[u >> 5][q] = val[q];
            }
        }
    }

    __syncthreads();
    if (u < 12) {
        out[(size_t)b * 12 + u] = (rsum[0][u] + rsum[1][u]) * oscale_s;
    }
}

extern "C" void kernel_launch(void* const* d_in, const int* in_sizes, int n_in,
                              void* d_out, int out_size) {
    const float* feats = (const float*)d_in[0];
    const float* qp    = (const float*)d_in[1];
    float* out         = (float*)d_out;
    qsim_kernel<<<4096, NT>>>(feats, qp, out);
}

// round 16
// speedup vs baseline: 1.0551x; 1.0551x over previous
#include <cuda_runtime.h>

#define NT 64
typedef unsigned long long u64;

__device__ __forceinline__ u64 pk2(float x, float y) {
    u64 r; asm("mov.b64 %0,{%1,%2};" : "=l"(r) : "f"(x), "f"(y)); return r;
}
__device__ __forceinline__ void upk2(u64 v, float& x, float& y) {
    asm("mov.b64 {%0,%1},%2;" : "=f"(x), "=f"(y) : "l"(v));
}
__device__ __forceinline__ u64 ffma2(u64 a, u64 b, u64 c) {
    u64 d; asm("fma.rn.f32x2 %0,%1,%2,%3;" : "=l"(d) : "l"(a), "l"(b), "l"(c)); return d;
}

// packed butterfly over pair-index bit B
template <int B>
__device__ __forceinline__ void vstage(u64* v, float t) {
    u64 tp = pk2(t, t), tn = pk2(-t, -t);
#pragma unroll
    for (int a = 0; a < 32; ++a)
        if (!(a & (1 << B))) {
            u64 A = v[a], Bv = v[a | (1 << B)];
            v[a]            = ffma2(tn, Bv, A);
            v[a | (1 << B)] = ffma2(tp, A, Bv);
        }
}

// register-pair index for pass-1 load row-pair q: a = (f0^{-1}(2q)) >> 1
__device__ __forceinline__ constexpr int AQ(int q) {
    int q0 = q & 1, q1 = (q >> 1) & 1, q2 = (q >> 2) & 1, q3 = (q >> 3) & 1, q4 = (q >> 4) & 1;
    return (q0 ^ q1 ^ q2) | ((q1 ^ q2) << 1) | ((q2 ^ q3 ^ q4) << 2)
         | ((q3 ^ q4) << 3) | (q4 << 4);
}

#define PITCH 68

__global__ void __launch_bounds__(NT, 11)
qsim_kernel(const float* __restrict__ feats,
            const float* __restrict__ qp,
            float* __restrict__ out)
{
    // layout T: element (i_lo, i_hi) at i_lo*PITCH + i_hi  (pad 68 -> bank rot by 4/row)
    __shared__ float buf[64 * PITCH];
    __shared__ float tt[240];
    __shared__ float wred[2], gred[2];
    __shared__ float oscale_s;
    __shared__ float rsum[2][12];

    const int u    = threadIdx.x;   // 0..63
    const int lane = u & 31;
    const int b    = blockIdx.x;

    // tan table + global cos product (cos factors -> output scale G^2)
    float gpart = 1.0f;
    for (int i = u; i < 240; i += NT) {
        float s, c; sincosf(0.5f * qp[12 + i], &s, &c);
        tt[i] = s / c; gpart *= c;
    }
#pragma unroll
    for (int o = 16; o; o >>= 1) gpart *= __shfl_xor_sync(~0u, gpart, o);
    if (lane == 0) gred[u >> 5] = gpart;

    // embedding: raw state into T layout (elem s at (s&63)*PITCH + (s>>6))
    const float2* f2 = reinterpret_cast<const float2*>(feats + (size_t)b * 2048);
    const float PIO2 = 1.5707963267948966f;
    float acc = 8.0f;
#pragma unroll
    for (int v = 0; v < 16; ++v) {
        int p = v * 64 + u;
        float2 x = f2[p];
        float y0 = tanhf(x.x) * PIO2;
        float y1 = tanhf(x.y) * PIO2;
        acc += y0 * y0 + y1 * y1;
        int s = 2 * p;
        buf[(s & 63) * PITCH + (s >> 6)]       = y0;
        buf[((s + 1) & 63) * PITCH + (s >> 6)] = y1;
    }
#pragma unroll
    for (int v = 16; v < 32; ++v) {
        int s = 2 * (v * 64 + u);
        buf[(s & 63) * PITCH + (s >> 6)]       = 0.5f;
        buf[((s + 1) & 63) * PITCH + (s >> 6)] = 0.5f;
    }
#pragma unroll
    for (int o = 16; o; o >>= 1) acc += __shfl_xor_sync(~0u, acc, o);
    if (lane == 0) wred[u >> 5] = acc;
    __syncthreads();
    if (u == 0) {
        float G = gred[0] * gred[1];
        oscale_s = (G * G) / (wred[0] + wred[1]);
    }

    // per-thread constants
    // i_hi = H(u) = Mhi^{-1}(u)
    int u0 = u & 1, u1 = (u >> 1) & 1, u2b = (u >> 2) & 1;
    int u3 = (u >> 3) & 1, u4 = (u >> 4) & 1, u5 = (u >> 5) & 1;
    int Hh = (u0 ^ u1) | ((u1 ^ u2b ^ u3) << 1) | ((u2b ^ u3) << 2)
           | ((u3 ^ u4 ^ u5) << 3) | ((u4 ^ u5) << 4) | (u5 << 5);
    int e = u0 ^ u1;                         // i6 of this thread's dst block
    const float* pL = buf + u;               // pass-1 load base (col u, + m*PITCH imm)
    float* B0 = buf + Hh + (e ? 32 * PITCH : 0);   // pass-1 store, rows 0..31
    float* B1 = buf + Hh + (e ? 0 : 32 * PITCH);   // pass-1 store, rows 32..63
    float* pld = buf + u * PITCH;            // pass-2 base (in-place)
    float esgn = e ? -1.0f : 1.0f;

#pragma unroll 1
    for (int L = 0; L < 20; ++L) {
        const float* tc = &tt[L * 12];

        // ===== pass 1: entangling gather (addressing-free) + RY qubits 11..6 =====
        u64 vr[32];
        {
            float t11 = tc[11];
            u64 tm = pk2(-t11, t11);
#pragma unroll
            for (int q = 0; q < 32; ++q) {
                float A = pL[(2 * q) * PITCH];
                float Bv = pL[(2 * q + 1) * PITCH];
                u64 ab = pk2(A, Bv), ba = pk2(Bv, A);
                // role: even row holds comp0 iff (q&1)==0 (compile-time select)
                vr[AQ(q)] = (q & 1) ? ffma2(tm, ab, ba) : ffma2(tm, ba, ab);
            }
        }
        vstage<0>(vr, tc[10]);
        vstage<1>(vr, tc[9]);
        vstage<2>(vr, tc[8]);
        vstage<3>(vr, tc[7]);
        vstage<4>(vr, esgn * tc[6]);   // e-swapped pairing on bit5 => R(-t)
        __syncthreads();               // all gathers done before rows are overwritten
#pragma unroll
        for (int a = 0; a < 16; ++a) {
            float x, y; upk2(vr[a], x, y);
            B0[(2 * a) * PITCH]     = x;
            B0[(2 * a + 1) * PITCH] = y;
        }
#pragma unroll
        for (int a = 16; a < 32; ++a) {
            float x, y; upk2(vr[a], x, y);
            B1[(2 * a - 32) * PITCH] = x;
            B1[(2 * a - 31) * PITCH] = y;
        }
        __syncthreads();

        // ===== pass 2: linear in-place, RY qubits 5..0 =====
        // fold q5 (component, scalar on fresh loads) and q4 (packed) into the load
        u64 vp[32];
        {
            float t5 = tc[5], t4 = tc[4];
            u64 tn4 = pk2(-t4, -t4), tp4 = pk2(t4, t4);
#pragma unroll
            for (int g = 0; g < 16; ++g) {
                float4 f = *reinterpret_cast<const float4*>(pld + 4 * g);
                float a0 = fmaf(-t5, f.y, f.x);
                float a1 = fmaf( t5, f.x, f.y);
                float b0 = fmaf(-t5, f.w, f.z);
                float b1 = fmaf( t5, f.z, f.w);
                u64 lo = pk2(a0, a1), hi = pk2(b0, b1);
                vp[2 * g]     = ffma2(tn4, hi, lo);   // q4 across i7
                vp[2 * g + 1] = ffma2(tp4, lo, hi);
            }
        }
        vstage<1>(vp, tc[3]);
        vstage<2>(vp, tc[2]);
        vstage<3>(vp, tc[1]);
        vstage<4>(vp, tc[0]);

        if (L < 19) {
#pragma unroll
            for (int g = 0; g < 16; ++g) {
                float x0, y0, x1, y1;
                upk2(vp[2 * g], x0, y0);
                upk2(vp[2 * g + 1], x1, y1);
                *reinterpret_cast<float4*>(pld + 4 * g) = make_float4(x0, y0, x1, y1);
            }
            __syncthreads();
        } else {
            // ===== expvals from registers =====
            // component = i6 (q5); pair bits b0..b4 = i7..i11 (q4..q0); u = i0..i5 (q11..q6)
            float S = 0.f, Ty = 0.f, T0 = 0.f, T1 = 0.f, T2 = 0.f, T3 = 0.f, T4 = 0.f;
#pragma unroll
            for (int a = 0; a < 32; ++a) {
                float x, y; upk2(vp[a], x, y);
                float px = x * x, py = y * y, ps = px + py;
                S += ps; Ty += py;
                if (a & 1)  T0 += ps;
                if (a & 2)  T1 += ps;
                if (a & 4)  T2 += ps;
                if (a & 8)  T3 += ps;
                if (a & 16) T4 += ps;
            }
            float val[12];
            val[0] = S - 2.f * T4;
            val[1] = S - 2.f * T3;
            val[2] = S - 2.f * T2;
            val[3] = S - 2.f * T1;
            val[4] = S - 2.f * T0;
            val[5] = S - 2.f * Ty;
#pragma unroll
            for (int q = 6; q < 12; ++q)
                val[q] = ((u >> (11 - q)) & 1) ? -S : S;
#pragma unroll
            for (int q = 0; q < 12; ++q) {
#pragma unroll
                for (int o = 16; o; o >>= 1)
                    val[q] += __shfl_xor_sync(~0u, val[q], o);
            }
            if (lane == 0) {
#pragma unroll
                for (int q = 0; q < 12; ++q) rsum[u >> 5][q] = val[q];
            }
        }
    }

    __syncthreads();
    if (u < 12) {
        out[(size_t)b * 12 + u] = (rsum[0][u] + rsum[1][u]) * oscale_s;
    }
}

extern "C" void kernel_launch(void* const* d_in, const int* in_sizes, int n_in,
                              void* d_out, int out_size) {
    const float* feats = (const float*)d_in[0];
    const float* qp    = (const float*)d_in[1];
    float* out         = (float*)d_out;
    qsim_kernel<<<4096, NT>>>(feats, qp, out);
}

// round 17
// speedup vs baseline: 1.0982x; 1.0409x over previous
#include <cuda_runtime.h>

#define NT 64
typedef unsigned long long u64;

__device__ __forceinline__ u64 pk2(float x, float y) {
    u64 r; asm("mov.b64 %0,{%1,%2};" : "=l"(r) : "f"(x), "f"(y)); return r;
}
__device__ __forceinline__ void upk2(u64 v, float& x, float& y) {
    asm("mov.b64 {%0,%1},%2;" : "=f"(x), "=f"(y) : "l"(v));
}
__device__ __forceinline__ u64 ffma2(u64 a, u64 b, u64 c) {
    u64 d; asm("fma.rn.f32x2 %0,%1,%2,%3;" : "=l"(d) : "l"(a), "l"(b), "l"(c)); return d;
}

// packed butterfly over pair-index bit B
template <int B>
__device__ __forceinline__ void vstage(u64* v, float t) {
    u64 tp = pk2(t, t), tn = pk2(-t, -t);
#pragma unroll
    for (int a = 0; a < 32; ++a)
        if (!(a & (1 << B))) {
            u64 A = v[a], Bv = v[a | (1 << B)];
            v[a]            = ffma2(tn, Bv, A);
            v[a | (1 << B)] = ffma2(tp, A, Bv);
        }
}

// register-pair index for pass-1 load row-pair q: a = (f0^{-1}(2q)) >> 1
__device__ __forceinline__ constexpr int AQ(int q) {
    int q0 = q & 1, q1 = (q >> 1) & 1, q2 = (q >> 2) & 1, q3 = (q >> 3) & 1, q4 = (q >> 4) & 1;
    return (q0 ^ q1 ^ q2) | ((q1 ^ q2) << 1) | ((q2 ^ q3 ^ q4) << 2)
         | ((q3 ^ q4) << 3) | (q4 << 4);
}

// PITCH 66: row stride = 33 8B-units == 1 (mod 16) -> LDS.64/STS.64 conflict-free;
// scalar accesses bank = (2*row + col) mod 32, distinct per lane. 8B alignment: 264*u.
#define PITCH 66

__global__ void __launch_bounds__(NT, 11)
qsim_kernel(const float* __restrict__ feats,
            const float* __restrict__ qp,
            float* __restrict__ out)
{
    // layout T: element (i_lo, i_hi) at i_lo*PITCH + i_hi
    __shared__ __align__(16) float buf[64 * PITCH];
    __shared__ float tt[240];
    __shared__ float wred[2], gred[2];
    __shared__ float oscale_s;
    __shared__ float rsum[2][12];

    const int u    = threadIdx.x;   // 0..63
    const int lane = u & 31;
    const int b    = blockIdx.x;

    // tan table + global cos product (cos factors -> output scale G^2)
    float gpart = 1.0f;
    for (int i = u; i < 240; i += NT) {
        float s, c; sincosf(0.5f * qp[12 + i], &s, &c);
        tt[i] = s / c; gpart *= c;
    }
#pragma unroll
    for (int o = 16; o; o >>= 1) gpart *= __shfl_xor_sync(~0u, gpart, o);
    if (lane == 0) gred[u >> 5] = gpart;

    // embedding: raw state into T layout (elem s at (s&63)*PITCH + (s>>6))
    const float2* f2 = reinterpret_cast<const float2*>(feats + (size_t)b * 2048);
    const float PIO2 = 1.5707963267948966f;
    float acc = 8.0f;
#pragma unroll
    for (int v = 0; v < 16; ++v) {
        int p = v * 64 + u;
        float2 x = f2[p];
        float y0 = tanhf(x.x) * PIO2;
        float y1 = tanhf(x.y) * PIO2;
        acc += y0 * y0 + y1 * y1;
        int s = 2 * p;
        buf[(s & 63) * PITCH + (s >> 6)]       = y0;
        buf[((s + 1) & 63) * PITCH + (s >> 6)] = y1;
    }
#pragma unroll
    for (int v = 16; v < 32; ++v) {
        int s = 2 * (v * 64 + u);
        buf[(s & 63) * PITCH + (s >> 6)]       = 0.5f;
        buf[((s + 1) & 63) * PITCH + (s >> 6)] = 0.5f;
    }
#pragma unroll
    for (int o = 16; o; o >>= 1) acc += __shfl_xor_sync(~0u, acc, o);
    if (lane == 0) wred[u >> 5] = acc;
    __syncthreads();
    if (u == 0) {
        float G = gred[0] * gred[1];
        oscale_s = (G * G) / (wred[0] + wred[1]);
    }

    // per-thread constants
    // i_hi = H(u) = Mhi^{-1}(u)
    int u0 = u & 1, u1 = (u >> 1) & 1, u2b = (u >> 2) & 1;
    int u3 = (u >> 3) & 1, u4 = (u >> 4) & 1, u5 = (u >> 5) & 1;
    int Hh = (u0 ^ u1) | ((u1 ^ u2b ^ u3) << 1) | ((u2b ^ u3) << 2)
           | ((u3 ^ u4 ^ u5) << 3) | ((u4 ^ u5) << 4) | (u5 << 5);
    int e = u0 ^ u1;                         // i6 of this thread's dst block
    const float* pL = buf + u;               // pass-1 load base (col u, + m*PITCH imm)
    float* B0 = buf + Hh + (e ? 32 * PITCH : 0);   // pass-1 store, rows 0..31
    float* B1 = buf + Hh + (e ? 0 : 32 * PITCH);   // pass-1 store, rows 32..63
    u64* pld2 = reinterpret_cast<u64*>(buf + u * PITCH);  // pass-2 base (64-bit, in-place)
    float esgn = e ? -1.0f : 1.0f;

#pragma unroll 1
    for (int L = 0; L < 20; ++L) {
        const float* tc = &tt[L * 12];

        // ===== pass 1: entangling gather (addressing-free) + RY qubits 11..6 =====
        u64 vr[32];
        {
            float t11 = tc[11];
            u64 tm = pk2(-t11, t11);
#pragma unroll
            for (int q = 0; q < 32; ++q) {
                float A = pL[(2 * q) * PITCH];
                float Bv = pL[(2 * q + 1) * PITCH];
                u64 ab = pk2(A, Bv), ba = pk2(Bv, A);
                // role: even row holds comp0 iff (q&1)==0 (compile-time select)
                vr[AQ(q)] = (q & 1) ? ffma2(tm, ab, ba) : ffma2(tm, ba, ab);
            }
        }
        vstage<0>(vr, tc[10]);
        vstage<1>(vr, tc[9]);
        vstage<2>(vr, tc[8]);
        vstage<3>(vr, tc[7]);
        vstage<4>(vr, esgn * tc[6]);   // e-swapped pairing on bit5 => R(-t)
        __syncthreads();               // all gathers done before rows are overwritten
#pragma unroll
        for (int a = 0; a < 16; ++a) {
            float x, y; upk2(vr[a], x, y);
            B0[(2 * a) * PITCH]     = x;
            B0[(2 * a + 1) * PITCH] = y;
        }
#pragma unroll
        for (int a = 16; a < 32; ++a) {
            float x, y; upk2(vr[a], x, y);
            B1[(2 * a - 32) * PITCH] = x;
            B1[(2 * a - 31) * PITCH] = y;
        }
        __syncthreads();

        // ===== pass 2: linear in-place (64-bit accesses), RY qubits 5..0 =====
        // fold q5 (component, scalar on fresh loads) and q4 (packed) into the load
        u64 vp[32];
        {
            float t5 = tc[5], t4 = tc[4];
            u64 tn4 = pk2(-t4, -t4), tp4 = pk2(t4, t4);
#pragma unroll
            for (int g = 0; g < 16; ++g) {
                u64 r0 = pld2[2 * g];
                u64 r1 = pld2[2 * g + 1];
                float fx, fy, fz, fw;
                upk2(r0, fx, fy);
                upk2(r1, fz, fw);
                float a0 = fmaf(-t5, fy, fx);
                float a1 = fmaf( t5, fx, fy);
                float b0 = fmaf(-t5, fw, fz);
                float b1 = fmaf( t5, fz, fw);
                u64 lo = pk2(a0, a1), hi = pk2(b0, b1);
                vp[2 * g]     = ffma2(tn4, hi, lo);   // q4 across i7
                vp[2 * g + 1] = ffma2(tp4, lo, hi);
            }
        }
        vstage<1>(vp, tc[3]);
        vstage<2>(vp, tc[2]);
        vstage<3>(vp, tc[1]);
        vstage<4>(vp, tc[0]);

        if (L < 19) {
#pragma unroll
            for (int g = 0; g < 16; ++g) {
                pld2[2 * g]     = vp[2 * g];      // STS.64 straight from the u64 pair
                pld2[2 * g + 1] = vp[2 * g + 1];
            }
            __syncthreads();
        } else {
            // ===== expvals from registers =====
            // component = i6 (q5); pair bits b0..b4 = i7..i11 (q4..q0); u = i0..i5 (q11..q6)
            float S = 0.f, Ty = 0.f, T0 = 0.f, T1 = 0.f, T2 = 0.f, T3 = 0.f, T4 = 0.f;
#pragma unroll
            for (int a = 0; a < 32; ++a) {
                float x, y; upk2(vp[a], x, y);
                float px = x * x, py = y * y, ps = px + py;
                S += ps; Ty += py;
                if (a & 1)  T0 += ps;
                if (a & 2)  T1 += ps;
                if (a & 4)  T2 += ps;
                if (a & 8)  T3 += ps;
                if (a & 16) T4 += ps;
            }
            float val[12];
            val[0] = S - 2.f * T4;
            val[1] = S - 2.f * T3;
            val[2] = S - 2.f * T2;
            val[3] = S - 2.f * T1;
            val[4] = S - 2.f * T0;
            val[5] = S - 2.f * Ty;
#pragma unroll
            for (int q = 6; q < 12; ++q)
                val[q] = ((u >> (11 - q)) & 1) ? -S : S;
#pragma unroll
            for (int q = 0; q < 12; ++q) {
#pragma unroll
                for (int o = 16; o; o >>= 1)
                    val[q] += __shfl_xor_sync(~0u, val[q], o);
            }
            if (lane == 0) {
#pragma unroll
                for (int q = 0; q < 12; ++q) rsum[u >> 5][q] = val[q];
            }
        }
    }

    __syncthreads();
    if (u < 12) {
        out[(size_t)b * 12 + u] = (rsum[0][u] + rsum[1][u]) * oscale_s;
    }
}

extern "C" void kernel_launch(void* const* d_in, const int* in_sizes, int n_in,
                              void* d_out, int out_size) {
    const float* feats = (const float*)d_in[0];
    const float* qp    = (const float*)d_in[1];
    float* out         = (float*)d_out;
    qsim_kernel<<<4096, NT>>>(feats, qp, out);
}